// round 5
// baseline (speedup 1.0000x reference)
#include <cuda_runtime.h>
#include <math.h>

namespace {

constexpr int T_     = 29;        // time samples per segment
constexpr int NSEG   = 3;
constexpr int B_     = 16384;
constexpr int TB     = 256;       // 8 warps/block
constexpr int NW     = TB / 32;
constexpr int TSPLIT = 4;         // t-range quarters (7,7,7,8 rows)
constexpr float DS_  = 0.005f;

// Compact constant-curvature transfer: R(s)=R0*M, r(s)=r0+R0*v, with
// M = [[m00,m01,by],[m01,m11,-bx],[-by,bx,ct]] (6 unique entries).
struct Xfer { float m00, m01, m11, bx, by, ct, v0, v1, v2; };

__device__ __forceinline__ Xfer curv(float ux, float uy, float s)
{
    float w2 = fmaf(ux, ux, uy * uy);
    float w  = sqrtf(w2);
    float th = s * w;
    float b, c;
    if (th < 1e-4f) {
        b = s;                      // sinθ/ω ≈ s
        c = 0.5f * s * s;           // (1-cosθ)/ω² ≈ s²/2
    } else {
        float sh, ch;
        __sincosf(0.5f * th, &sh, &ch);       // MUFU.SIN/COS
        float rw = __fdividef(1.0f, w);
        b = (2.0f * sh * ch) * rw;            // sinθ/ω
        c = (2.0f * sh * sh) * rw * rw;       // (1-cosθ)/ω², cancellation-free
    }
    Xfer x;
    x.ct = fmaf(-c, w2, 1.0f);                // cosθ
    x.bx = b * ux;  x.by = b * uy;
    float cx = c * ux, cy = c * uy;
    x.m00 = fmaf(-cy, uy, 1.0f);
    x.m01 = cx * uy;
    x.m11 = fmaf(-cx, ux, 1.0f);
    x.v0 = cy;  x.v1 = -cx;  x.v2 = b;
    return x;
}

__device__ __forceinline__ void apply(float r[3], float R[9], const Xfer& x)
{
#pragma unroll
    for (int i = 0; i < 3; i++) {
        float a0 = R[3 * i], a1 = R[3 * i + 1], a2 = R[3 * i + 2];
        r[i] += a0 * x.v0 + a1 * x.v1 + a2 * x.v2;
        R[3 * i]     = a0 * x.m00 + a1 * x.m01 - a2 * x.by;
        R[3 * i + 1] = a0 * x.m01 + a1 * x.m11 + a2 * x.bx;
        R[3 * i + 2] = a0 * x.by  - a1 * x.bx  + a2 * x.ct;
    }
}

__device__ __forceinline__ void advance(float r[3], float R[9],
                                        float ux, float uy, float s)
{
    Xfer x = curv(ux, uy, s);
    apply(r, R, x);
}

__global__ void __launch_bounds__(TB, 6)
pcc_kernel(const float* __restrict__ actions, float* __restrict__ out)
{
    // per-warp tile: 2 rows x 32 elems x 14 floats = 896 floats (3584B)
    __shared__ float sm[NW][2 * 32 * 14];
    const int tid  = threadIdx.x;
    const int lane = tid & 31;
    const int w    = tid >> 5;
    const int bx   = blockIdx.x;
    const int seg  = blockIdx.y / TSPLIT;
    const int tq   = blockIdx.y - seg * TSPLIT;
    const int t0   = (tq * T_) / TSPLIT;
    const int t1   = ((tq + 1) * T_) / TSPLIT;
    const int b0   = bx * TB;

    // Stage actions coalesced through smem (stride-9 reads conflict-free).
    float* stage = &sm[0][0];
#pragma unroll
    for (int i = 0; i < 9; i++)
        stage[tid + i * TB] = actions[(size_t)b0 * 9 + tid + i * TB];
    __syncthreads();
    float a[9];
#pragma unroll
    for (int i = 0; i < 9; i++) a[i] = stage[tid * 9 + i];
    __syncthreads();

    // Chain through prior segments (clamped endpoints), pick up own params.
    float r[3] = {0.f, 0.f, 0.f};
    float R[9] = {1.f, 0.f, 0.f, 0.f, 1.f, 0.f, 0.f, 0.f, 1.f};
    float ux = 0.f, uy = 0.f;
    int len = 0;
#pragma unroll
    for (int n = 0; n < NSEG; n++) {
        if (n > seg) break;
        float l  = 0.1f + a[3 * n];
        float ld = l * 0.0075f;
        ux  = __fdividef(a[3 * n + 2], -ld);
        uy  = __fdividef(a[3 * n + 1],  ld);
        len = (int)(l / DS_);           // IEEE-exact: replicates (l/DS).astype(int32)
        if (n < seg) advance(r, R, ux, uy, (float)len * DS_);
    }

    // Jump to this t-range's start (clamped), precompute the constant step.
    int tt0 = t0 < len ? t0 : len;
    advance(r, R, ux, uy, (float)tt0 * DS_);
    const Xfer step = curv(ux, uy, DS_);

    float* tile = &sm[w][0];
    float4* tile4 = reinterpret_cast<float4*>(tile);

    auto pack = [&](int h) {
        float2* pk = reinterpret_cast<float2*>(tile + h * 448 + lane * 14);
        pk[0] = make_float2(r[0], r[1]);
        pk[1] = make_float2(r[2], R[0]);
        pk[2] = make_float2(R[1], R[2]);
        pk[3] = make_float2(R[3], R[4]);
        pk[4] = make_float2(R[5], R[6]);
        pk[5] = make_float2(R[7], R[8]);
        pk[6] = make_float2(ux,   uy);
    };

    const size_t rowstride4 = (size_t)B_ * 14 / 4;   // float4 per row
    float4* obase = reinterpret_cast<float4*>(out)
                  + (size_t)(b0 + w * 32) * 14 / 4;

    int t = t0;
    for (; t + 1 < t1; t += 2) {
        __syncwarp();                 // prior iteration's LDS done before STS
        pack(0);
        if (t < len) apply(r, R, step);
        pack(1);
        __syncwarp();

        // copy out both rows: lanes 0-15 -> row t, lanes 16-31 -> row t+1
        float4* dst = obase + (size_t)(seg * T_ + t + (lane >> 4)) * rowstride4;
        int l16 = lane & 15;
        int sbase = (lane >> 4) * 112;
#pragma unroll
        for (int i = 0; i < 7; i++)
            dst[l16 + i * 16] = tile4[sbase + l16 + i * 16];

        if (t + 1 < len) apply(r, R, step);
    }
    if (t < t1) {                     // tail single row
        __syncwarp();
        pack(0);
        __syncwarp();
        float4* dst = obase + (size_t)(seg * T_ + t) * rowstride4;
#pragma unroll
        for (int i = 0; i < 3; i++)
            dst[lane + i * 32] = tile4[lane + i * 32];
        if (lane < 16) dst[96 + lane] = tile4[96 + lane];
    }
}

} // namespace

extern "C" void kernel_launch(void* const* d_in, const int* in_sizes, int n_in,
                              void* d_out, int out_size)
{
    (void)in_sizes; (void)n_in; (void)out_size;
    const float* actions = (const float*)d_in[0];
    float* out = (float*)d_out;
    dim3 grid(B_ / TB, NSEG * TSPLIT);
    pcc_kernel<<<grid, TB>>>(actions, out);
}

// round 6
// speedup vs baseline: 1.2751x; 1.2751x over previous
#include <cuda_runtime.h>
#include <math.h>

namespace {

constexpr int T_     = 29;        // time samples per segment
constexpr int NSEG   = 3;
constexpr int B_     = 16384;
constexpr int TB     = 256;       // 8 warps/block
constexpr int NW     = TB / 32;
constexpr int TSPLIT = 4;         // t-range quarters (7,7,7,8 rows)
constexpr float DS_  = 0.005f;

// Compact constant-curvature transfer: R(s)=R0*M, r(s)=r0+R0*v, with
// M = [[m00,m01,by],[m01,m11,-bx],[-by,bx,ct]] (6 unique entries).
struct Xfer { float m00, m01, m11, bx, by, ct, v0, v1, v2; };

__device__ __forceinline__ Xfer curv(float ux, float uy, float s)
{
    float w2 = fmaf(ux, ux, uy * uy);
    float w  = sqrtf(w2);
    float th = s * w;
    float b, c;
    if (th < 1e-4f) {
        b = s;                      // sinθ/ω ≈ s
        c = 0.5f * s * s;           // (1-cosθ)/ω² ≈ s²/2
    } else {
        float sh, ch;
        __sincosf(0.5f * th, &sh, &ch);       // MUFU.SIN/COS
        float rw = __fdividef(1.0f, w);
        b = (2.0f * sh * ch) * rw;            // sinθ/ω
        c = (2.0f * sh * sh) * rw * rw;       // (1-cosθ)/ω², cancellation-free
    }
    Xfer x;
    x.ct = fmaf(-c, w2, 1.0f);                // cosθ
    x.bx = b * ux;  x.by = b * uy;
    float cx = c * ux, cy = c * uy;
    x.m00 = fmaf(-cy, uy, 1.0f);
    x.m01 = cx * uy;
    x.m11 = fmaf(-cx, ux, 1.0f);
    x.v0 = cy;  x.v1 = -cx;  x.v2 = b;
    return x;
}

__device__ __forceinline__ void apply(float r[3], float R[9], const Xfer& x)
{
#pragma unroll
    for (int i = 0; i < 3; i++) {
        float a0 = R[3 * i], a1 = R[3 * i + 1], a2 = R[3 * i + 2];
        r[i] += a0 * x.v0 + a1 * x.v1 + a2 * x.v2;
        R[3 * i]     = a0 * x.m00 + a1 * x.m01 - a2 * x.by;
        R[3 * i + 1] = a0 * x.m01 + a1 * x.m11 + a2 * x.bx;
        R[3 * i + 2] = a0 * x.by  - a1 * x.bx  + a2 * x.ct;
    }
}

__device__ __forceinline__ void advance(float r[3], float R[9],
                                        float ux, float uy, float s)
{
    Xfer x = curv(ux, uy, s);
    apply(r, R, x);
}

__global__ void __launch_bounds__(TB, 6)
pcc_kernel(const float* __restrict__ actions, float* __restrict__ out)
{
    // per-warp double-buffered 32x14 tiles; region 0 also stages actions
    __shared__ float sm[NW][2][32 * 14];
    const int tid  = threadIdx.x;
    const int lane = tid & 31;
    const int w    = tid >> 5;
    const int bx   = blockIdx.x;
    const int seg  = blockIdx.y / TSPLIT;
    const int tq   = blockIdx.y - seg * TSPLIT;
    const int t0   = (tq * T_) / TSPLIT;
    const int t1   = ((tq + 1) * T_) / TSPLIT;
    const int b0   = bx * TB;

    // Stage actions coalesced through smem (stride-9 reads conflict-free:
    // gcd(9,32)=1). Block-wide barriers only here.
    float* stage = &sm[0][0][0];
#pragma unroll
    for (int i = 0; i < 9; i++)
        stage[tid + i * TB] = actions[(size_t)b0 * 9 + tid + i * TB];
    __syncthreads();
    float a[9];
#pragma unroll
    for (int i = 0; i < 9; i++) a[i] = stage[tid * 9 + i];
    __syncthreads();

    // Chain through prior segments (clamped endpoints), pick up own params.
    float r[3] = {0.f, 0.f, 0.f};
    float R[9] = {1.f, 0.f, 0.f, 0.f, 1.f, 0.f, 0.f, 0.f, 1.f};
    float ux = 0.f, uy = 0.f;
    int len = 0;
#pragma unroll
    for (int n = 0; n < NSEG; n++) {
        if (n > seg) break;
        float l  = 0.1f + a[3 * n];
        float ld = l * 0.0075f;
        ux  = __fdividef(a[3 * n + 2], -ld);
        uy  = __fdividef(a[3 * n + 1],  ld);
        len = (int)(l / DS_);           // IEEE-exact: replicates (l/DS).astype(int32)
        if (n < seg) advance(r, R, ux, uy, (float)len * DS_);
    }

    // Jump to this t-range's start (clamped), precompute the constant step.
    int tt0 = t0 < len ? t0 : len;
    advance(r, R, ux, uy, (float)tt0 * DS_);
    const Xfer step = curv(ux, uy, DS_);

    for (int t = t0; t < t1; ++t) {
        float* tile = &sm[w][(t - t0) & 1][0];
        // pack state as 7 float2: (r0,r1)(r2,R0)(R1,R2)(R3,R4)(R5,R6)(R7,R8)(ux,uy)
        float2* pk = reinterpret_cast<float2*>(tile + lane * 14);
        pk[0] = make_float2(r[0], r[1]);
        pk[1] = make_float2(r[2], R[0]);
        pk[2] = make_float2(R[1], R[2]);
        pk[3] = make_float2(R[3], R[4]);
        pk[4] = make_float2(R[5], R[6]);
        pk[5] = make_float2(R[7], R[8]);
        pk[6] = make_float2(ux,   uy);
        __syncwarp();

        const float2* src = reinterpret_cast<const float2*>(tile);
        float2* dst = reinterpret_cast<float2*>(
            out + (size_t)(seg * T_ + t) * ((size_t)B_ * 14)
                + (size_t)(b0 + w * 32) * 14);
#pragma unroll
        for (int i = 0; i < 7; i++)
            dst[lane + i * 32] = src[lane + i * 32];

        if (t < len) apply(r, R, step);   // overlaps with LDS/STG above
    }
}

} // namespace

extern "C" void kernel_launch(void* const* d_in, const int* in_sizes, int n_in,
                              void* d_out, int out_size)
{
    (void)in_sizes; (void)n_in; (void)out_size;
    const float* actions = (const float*)d_in[0];
    float* out = (float*)d_out;
    dim3 grid(B_ / TB, NSEG * TSPLIT);
    pcc_kernel<<<grid, TB>>>(actions, out);
}